// round 16
// baseline (speedup 1.0000x reference)
#include <cuda_runtime.h>
#include <cstdint>

#define N_NODES 100000
#define N_EDGES 1600000
#define NF 128
#define SCAN_B 1024
#define SCAN_NBLK ((N_NODES + SCAN_B - 1) / SCAN_B)   // 98

// Scratch (__device__ globals only; no allocation anywhere).
__device__ float g_h[(size_t)N_NODES * NF];   // h = x @ W
__device__ int   g_cnt[N_NODES];
__device__ int   g_excl[N_NODES];
__device__ int   g_blksum[SCAN_NBLK];
__device__ int   g_blkoff[SCAN_NBLK];
__device__ int   g_rowptr[N_NODES + 1];
__device__ int   g_cur[N_NODES];
__device__ int   g_esrc[N_EDGES];
__device__ float g_dinv[N_NODES];
__device__ int   g_is64;

// ---------------------------------------------------------------------------
__global__ void detect_idx_kernel(const int* __restrict__ ei32) {
    if (threadIdx.x == 0) {
        int any_odd_nonzero = 0;
        #pragma unroll
        for (int i = 1; i < 64; i += 2)
            if (ei32[i] != 0) any_odd_nonzero = 1;
        g_is64 = any_odd_nonzero ? 0 : 1;
    }
}

__global__ void zero_cnt_kernel() {
    int i = blockIdx.x * blockDim.x + threadIdx.x;
    if (i < N_NODES) g_cnt[i] = 0;
}

__global__ __launch_bounds__(256) void count_deg_kernel(const int* __restrict__ ei32) {
    const int stride = g_is64 ? 2 : 1;
    const long long dstbase = g_is64 ? (2LL * N_EDGES) : (long long)N_EDGES;
    int base = 4 * (blockIdx.x * blockDim.x + threadIdx.x);
    #pragma unroll
    for (int j = 0; j < 4; j++) {
        int e = base + j;
        if (e < N_EDGES)
            atomicAdd(&g_cnt[ei32[dstbase + (long long)stride * e]], 1);
    }
}

__global__ __launch_bounds__(SCAN_B) void scan_a_kernel() {
    __shared__ int sd[SCAN_B];
    const int tid = threadIdx.x;
    const int i = blockIdx.x * SCAN_B + tid;
    int v = (i < N_NODES) ? g_cnt[i] : 0;
    sd[tid] = v;
    __syncthreads();
    #pragma unroll
    for (int off = 1; off < SCAN_B; off <<= 1) {
        int t = (tid >= off) ? sd[tid - off] : 0;
        __syncthreads();
        sd[tid] += t;
        __syncthreads();
    }
    if (i < N_NODES) g_excl[i] = sd[tid] - v;
    if (tid == SCAN_B - 1) g_blksum[blockIdx.x] = sd[tid];
}

__global__ void scan_b_kernel() {
    if (threadIdx.x == 0) {
        int run = 0;
        for (int k = 0; k < SCAN_NBLK; k++) { g_blkoff[k] = run; run += g_blksum[k]; }
    }
}

__global__ void scan_c_kernel() {
    int i = blockIdx.x * blockDim.x + threadIdx.x;
    if (i < N_NODES) {
        int rp = g_excl[i] + g_blkoff[i >> 10];
        g_rowptr[i] = rp;
        g_cur[i] = rp;
        g_dinv[i] = rsqrtf((float)(g_cnt[i] + 1));
        if (i == 0) g_rowptr[N_NODES] = N_EDGES;
    }
}

__global__ __launch_bounds__(256) void place_kernel(const int* __restrict__ ei32) {
    const int stride = g_is64 ? 2 : 1;
    const long long dstbase = g_is64 ? (2LL * N_EDGES) : (long long)N_EDGES;
    int base = 4 * (blockIdx.x * blockDim.x + threadIdx.x);
    #pragma unroll
    for (int j = 0; j < 4; j++) {
        int e = base + j;
        if (e < N_EDGES) {
            int s = ei32[(long long)stride * e];
            int d = ei32[dstbase + (long long)stride * e];
            int slot = atomicAdd(&g_cur[d], 1);
            g_esrc[slot] = s;
        }
    }
}

// ---------------------------------------------------------------------------
// GEMM: g_h = x @ W. f32x2 register tile packed along ROW-PAIRS:
//   x row-pair {x_2p, x_2p+1} read directly with one broadcast LDS.64
//   (adjacent in xsT[kk][*], stride 66 = even -> 8B aligned).
//   Per kk: 1 LDS.128 (W) + 4 LDS.64 (x pairs) + 4 W packs + 16 FMA2
//   = 25 issues (vs 33 in col-pair version).
#define BM 64
#define KC 32
__global__ __launch_bounds__(256) void gemm_kernel(
    const float* __restrict__ x, const float* __restrict__ W)
{
    __shared__ float xsT[KC][BM + 2];   // stride 66: even (8B pairs), 2-way store conflict only
    __shared__ float ws[KC][NF];

    const int tid = threadIdx.x;
    const int tn  = tid & 31;           // col group: cols 4*tn .. 4*tn+3
    const int tm  = tid >> 5;           // row group: rows 8*tm .. 8*tm+7
    const int row0 = blockIdx.x * BM;

    // acc[p][c] = f32x2 over rows {8*tm+2p, 8*tm+2p+1}, col 4*tn+c
    unsigned long long acc[4][4];
    #pragma unroll
    for (int p = 0; p < 4; p++)
        #pragma unroll
        for (int c = 0; c < 4; c++) acc[p][c] = 0ull;

    for (int k0 = 0; k0 < NF; k0 += KC) {
        #pragma unroll
        for (int t = 0; t < 8; t++) {
            int idx = tid + t * 256;          // 0..2047
            int kk = idx & 31;
            int r  = idx >> 5;
            int rg = row0 + r;
            xsT[kk][r] = (rg < N_NODES) ? x[(size_t)rg * NF + k0 + kk] : 0.0f;
        }
        #pragma unroll
        for (int t = 0; t < 16; t++) {
            int idx = tid + t * 256;          // 0..4095
            int k = idx >> 7;
            int c = idx & 127;
            ws[k][c] = W[(size_t)(k0 + k) * NF + c];
        }
        __syncthreads();

        #pragma unroll 8
        for (int kk = 0; kk < KC; kk++) {
            const float4 wq = *reinterpret_cast<const float4*>(&ws[kk][tn * 4]);
            unsigned long long w2[4];
            asm("mov.b64 %0, {%1, %1};" : "=l"(w2[0]) : "f"(wq.x));
            asm("mov.b64 %0, {%1, %1};" : "=l"(w2[1]) : "f"(wq.y));
            asm("mov.b64 %0, {%1, %1};" : "=l"(w2[2]) : "f"(wq.z));
            asm("mov.b64 %0, {%1, %1};" : "=l"(w2[3]) : "f"(wq.w));
            #pragma unroll
            for (int p = 0; p < 4; p++) {
                const unsigned long long x2 =
                    *reinterpret_cast<const unsigned long long*>(&xsT[kk][tm * 8 + 2 * p]);
                asm("fma.rn.f32x2 %0, %1, %2, %0;"
                    : "+l"(acc[p][0]) : "l"(x2), "l"(w2[0]));
                asm("fma.rn.f32x2 %0, %1, %2, %0;"
                    : "+l"(acc[p][1]) : "l"(x2), "l"(w2[1]));
                asm("fma.rn.f32x2 %0, %1, %2, %0;"
                    : "+l"(acc[p][2]) : "l"(x2), "l"(w2[2]));
                asm("fma.rn.f32x2 %0, %1, %2, %0;"
                    : "+l"(acc[p][3]) : "l"(x2), "l"(w2[3]));
            }
        }
        __syncthreads();
    }

    // epilogue: unpack row pairs -> two float4 rows per p
    #pragma unroll
    for (int p = 0; p < 4; p++) {
        float4 vlo, vhi;
        asm("mov.b64 {%0, %1}, %2;" : "=f"(vlo.x), "=f"(vhi.x) : "l"(acc[p][0]));
        asm("mov.b64 {%0, %1}, %2;" : "=f"(vlo.y), "=f"(vhi.y) : "l"(acc[p][1]));
        asm("mov.b64 {%0, %1}, %2;" : "=f"(vlo.z), "=f"(vhi.z) : "l"(acc[p][2]));
        asm("mov.b64 {%0, %1}, %2;" : "=f"(vlo.w), "=f"(vhi.w) : "l"(acc[p][3]));
        const int r0 = row0 + tm * 8 + 2 * p;
        if (r0 < N_NODES)
            *reinterpret_cast<float4*>(&g_h[(size_t)r0 * NF + tn * 4]) = vlo;
        if (r0 + 1 < N_NODES)
            *reinterpret_cast<float4*>(&g_h[(size_t)(r0 + 1) * NF + tn * 4]) = vhi;
    }
}

// ---------------------------------------------------------------------------
// Gather: one block per dst node, thread = feature column. No atomics.
// (R10 simple version — proven best.)
#define ETILE 128
__global__ __launch_bounds__(128) void gather_kernel(
    const float* __restrict__ b, float* __restrict__ out)
{
    __shared__ int   ss[ETILE];
    __shared__ float sv[ETILE];

    const int d = blockIdx.x;
    const int c = threadIdx.x;
    const int start = g_rowptr[d];
    const int end   = g_rowptr[d + 1];
    const float dinv_d = g_dinv[d];

    float acc = dinv_d * g_h[(size_t)d * NF + c];   // self loop

    for (int t = start; t < end; t += ETILE) {
        const int n = min(ETILE, end - t);
        if (c < n) {
            int s = g_esrc[t + c];
            ss[c] = s;
            sv[c] = g_dinv[s];
        }
        __syncthreads();
        for (int j = 0; j < n; j++) {
            acc = fmaf(g_h[(size_t)ss[j] * NF + c], sv[j], acc);
        }
        __syncthreads();
    }

    out[(size_t)d * NF + c] = b[c] + dinv_d * acc;
}

// ---------------------------------------------------------------------------
extern "C" void kernel_launch(void* const* d_in, const int* in_sizes, int n_in,
                              void* d_out, int out_size) {
    const float* x    = (const float*)d_in[0];
    const int*   ei32 = (const int*)d_in[1];
    const float* W    = (const float*)d_in[2];
    const float* b    = (const float*)d_in[3];
    float*       out  = (float*)d_out;

    detect_idx_kernel<<<1, 32>>>(ei32);
    zero_cnt_kernel<<<(N_NODES + 255) / 256, 256>>>();
    count_deg_kernel<<<(N_EDGES / 4 + 255) / 256, 256>>>(ei32);
    // position 4: ncu capture slot -> profile the GEMM
    gemm_kernel<<<(N_NODES + BM - 1) / BM, 256>>>(x, W);
    scan_a_kernel<<<SCAN_NBLK, SCAN_B>>>();
    scan_b_kernel<<<1, 32>>>();
    scan_c_kernel<<<(N_NODES + 255) / 256, 256>>>();
    place_kernel<<<(N_EDGES / 4 + 255) / 256, 256>>>(ei32);
    gather_kernel<<<N_NODES, 128>>>(b, out);
}

// round 17
// speedup vs baseline: 1.0169x; 1.0169x over previous
#include <cuda_runtime.h>
#include <cstdint>

#define N_NODES 100000
#define N_EDGES 1600000
#define NF 128
#define SCAN_B 1024
#define SCAN_NBLK ((N_NODES + SCAN_B - 1) / SCAN_B)   // 98

// Scratch (__device__ globals only; no allocation anywhere).
__device__ float  g_h[(size_t)N_NODES * NF];   // h = x @ W
__device__ int    g_cnt[N_NODES];
__device__ int    g_excl[N_NODES];
__device__ int    g_blksum[SCAN_NBLK];
__device__ int    g_blkoff[SCAN_NBLK];
__device__ int    g_rowptr[N_NODES + 1];
__device__ int    g_cur[N_NODES];
__device__ int    g_esrc[N_EDGES];
__device__ float  g_dinv[N_NODES];
__device__ int    g_is64;
// Precomputed W fragments for m16n8k8 tf32 mma: [kstep 16][ntile 16][lane 32]
// float4 = {b0_hi, b1_hi, b0_lo, b1_lo} (tf32 bit patterns stored as float)
__device__ float4 g_wfrag[16 * 16 * 32];

// ---------------------------------------------------------------------------
__device__ __forceinline__ uint32_t f2tf32(float v) {
    uint32_t r;
    asm("cvt.rna.tf32.f32 %0, %1;" : "=r"(r) : "f"(v));
    return r;
}

// ---------------------------------------------------------------------------
__global__ void detect_idx_kernel(const int* __restrict__ ei32) {
    if (threadIdx.x == 0) {
        int any_odd_nonzero = 0;
        #pragma unroll
        for (int i = 1; i < 64; i += 2)
            if (ei32[i] != 0) any_odd_nonzero = 1;
        g_is64 = any_odd_nonzero ? 0 : 1;
    }
}

// Precompute W fragments (hi/lo tf32 split). 256 warps: one per (kstep, ntile).
__global__ __launch_bounds__(256) void wfrag_kernel(const float* __restrict__ W) {
    const int wid  = blockIdx.x * 8 + (threadIdx.x >> 5);  // 0..255
    const int lane = threadIdx.x & 31;
    const int gid  = lane >> 2;        // n within tile
    const int tig  = lane & 3;         // k within half
    const int ks   = wid >> 4;         // kstep 0..15
    const int nt   = wid & 15;         // ntile 0..15

    const float b0 = W[(size_t)(ks * 8 + tig)     * NF + nt * 8 + gid];
    const float b1 = W[(size_t)(ks * 8 + tig + 4) * NF + nt * 8 + gid];

    const uint32_t b0h = f2tf32(b0);
    const uint32_t b1h = f2tf32(b1);
    const uint32_t b0l = f2tf32(b0 - __uint_as_float(b0h));
    const uint32_t b1l = f2tf32(b1 - __uint_as_float(b1h));

    float4 v;
    v.x = __uint_as_float(b0h);
    v.y = __uint_as_float(b1h);
    v.z = __uint_as_float(b0l);
    v.w = __uint_as_float(b1l);
    g_wfrag[(ks * 16 + nt) * 32 + lane] = v;
}

__global__ void zero_cnt_kernel() {
    int i = blockIdx.x * blockDim.x + threadIdx.x;
    if (i < N_NODES) g_cnt[i] = 0;
}

// ---------------------------------------------------------------------------
// GEMM: g_h = x @ W via tf32 tensor-core mma (3xTF32 for fp32-like accuracy).
// Block 256 thr = 8 warps; tile M=128 x N=128; warp -> 16 rows, full N.
#define GM 128
__global__ __launch_bounds__(256) void gemm_kernel(const float* __restrict__ x) {
    __shared__ float xs[GM][36];   // stride 36: frag loads bank = 4*gid+tig, conflict-free

    const int tid  = threadIdx.x;
    const int warp = tid >> 5;
    const int lane = tid & 31;
    const int gid  = lane >> 2;
    const int tig  = lane & 3;
    const int wrow = warp * 16;
    const int rowbase = blockIdx.x * GM;

    float c[16][4];
    #pragma unroll
    for (int nt = 0; nt < 16; nt++)
        #pragma unroll
        for (int i = 0; i < 4; i++) c[nt][i] = 0.0f;

    for (int kc = 0; kc < NF; kc += 32) {
        // stage x chunk: 128 rows x 32 k (16 elem/thread, coalesced)
        #pragma unroll
        for (int t = 0; t < 16; t++) {
            int idx = tid + t * 256;          // 0..4095
            int r  = idx >> 5;
            int kk = idx & 31;
            int rg = rowbase + r;
            xs[r][kk] = (rg < N_NODES) ? x[(size_t)rg * NF + kc + kk] : 0.0f;
        }
        __syncthreads();

        #pragma unroll
        for (int ks = 0; ks < 4; ks++) {
            const int k0 = ks * 8;
            // A fragment (m16k8), conflict-free LDS
            const float a0f = xs[wrow + gid    ][k0 + tig];
            const float a1f = xs[wrow + 8 + gid][k0 + tig];
            const float a2f = xs[wrow + gid    ][k0 + tig + 4];
            const float a3f = xs[wrow + 8 + gid][k0 + tig + 4];
            uint32_t ah[4], al[4];
            ah[0] = f2tf32(a0f); al[0] = f2tf32(a0f - __uint_as_float(ah[0]));
            ah[1] = f2tf32(a1f); al[1] = f2tf32(a1f - __uint_as_float(ah[1]));
            ah[2] = f2tf32(a2f); al[2] = f2tf32(a2f - __uint_as_float(ah[2]));
            ah[3] = f2tf32(a3f); al[3] = f2tf32(a3f - __uint_as_float(ah[3]));

            const int ksg = (kc >> 3) + ks;   // global kstep 0..15
            const float4* wfp = &g_wfrag[(ksg * 16) * 32 + lane];

            #pragma unroll
            for (int nt = 0; nt < 16; nt++) {
                const float4 wf = wfp[nt * 32];
                const uint32_t b0h = __float_as_uint(wf.x);
                const uint32_t b1h = __float_as_uint(wf.y);
                const uint32_t b0l = __float_as_uint(wf.z);
                const uint32_t b1l = __float_as_uint(wf.w);
                // c += ah*bh + ah*bl + al*bh   (3xTF32)
                asm("mma.sync.aligned.m16n8k8.row.col.f32.tf32.tf32.f32 "
                    "{%0,%1,%2,%3}, {%4,%5,%6,%7}, {%8,%9}, {%0,%1,%2,%3};"
                    : "+f"(c[nt][0]), "+f"(c[nt][1]), "+f"(c[nt][2]), "+f"(c[nt][3])
                    : "r"(ah[0]), "r"(ah[1]), "r"(ah[2]), "r"(ah[3]), "r"(b0h), "r"(b1h));
                asm("mma.sync.aligned.m16n8k8.row.col.f32.tf32.tf32.f32 "
                    "{%0,%1,%2,%3}, {%4,%5,%6,%7}, {%8,%9}, {%0,%1,%2,%3};"
                    : "+f"(c[nt][0]), "+f"(c[nt][1]), "+f"(c[nt][2]), "+f"(c[nt][3])
                    : "r"(ah[0]), "r"(ah[1]), "r"(ah[2]), "r"(ah[3]), "r"(b0l), "r"(b1l));
                asm("mma.sync.aligned.m16n8k8.row.col.f32.tf32.tf32.f32 "
                    "{%0,%1,%2,%3}, {%4,%5,%6,%7}, {%8,%9}, {%0,%1,%2,%3};"
                    : "+f"(c[nt][0]), "+f"(c[nt][1]), "+f"(c[nt][2]), "+f"(c[nt][3])
                    : "r"(al[0]), "r"(al[1]), "r"(al[2]), "r"(al[3]), "r"(b0h), "r"(b1h));
            }
        }
        __syncthreads();
    }

    // epilogue: c[nt] -> g_h rows (gid, gid+8), cols nt*8 + tig*2 (+1)
    const int r0 = rowbase + wrow + gid;
    const int r1 = r0 + 8;
    #pragma unroll
    for (int nt = 0; nt < 16; nt++) {
        const int col = nt * 8 + tig * 2;
        if (r0 < N_NODES)
            *reinterpret_cast<float2*>(&g_h[(size_t)r0 * NF + col]) =
                make_float2(c[nt][0], c[nt][1]);
        if (r1 < N_NODES)
            *reinterpret_cast<float2*>(&g_h[(size_t)r1 * NF + col]) =
                make_float2(c[nt][2], c[nt][3]);
    }
}

// ---------------------------------------------------------------------------
__global__ __launch_bounds__(256) void count_deg_kernel(const int* __restrict__ ei32) {
    const int stride = g_is64 ? 2 : 1;
    const long long dstbase = g_is64 ? (2LL * N_EDGES) : (long long)N_EDGES;
    int base = 4 * (blockIdx.x * blockDim.x + threadIdx.x);
    #pragma unroll
    for (int j = 0; j < 4; j++) {
        int e = base + j;
        if (e < N_EDGES)
            atomicAdd(&g_cnt[ei32[dstbase + (long long)stride * e]], 1);
    }
}

__global__ __launch_bounds__(SCAN_B) void scan_a_kernel() {
    __shared__ int sd[SCAN_B];
    const int tid = threadIdx.x;
    const int i = blockIdx.x * SCAN_B + tid;
    int v = (i < N_NODES) ? g_cnt[i] : 0;
    sd[tid] = v;
    __syncthreads();
    #pragma unroll
    for (int off = 1; off < SCAN_B; off <<= 1) {
        int t = (tid >= off) ? sd[tid - off] : 0;
        __syncthreads();
        sd[tid] += t;
        __syncthreads();
    }
    if (i < N_NODES) g_excl[i] = sd[tid] - v;
    if (tid == SCAN_B - 1) g_blksum[blockIdx.x] = sd[tid];
}

__global__ void scan_b_kernel() {
    if (threadIdx.x == 0) {
        int run = 0;
        for (int k = 0; k < SCAN_NBLK; k++) { g_blkoff[k] = run; run += g_blksum[k]; }
    }
}

__global__ void scan_c_kernel() {
    int i = blockIdx.x * blockDim.x + threadIdx.x;
    if (i < N_NODES) {
        int rp = g_excl[i] + g_blkoff[i >> 10];
        g_rowptr[i] = rp;
        g_cur[i] = rp;
        g_dinv[i] = rsqrtf((float)(g_cnt[i] + 1));
        if (i == 0) g_rowptr[N_NODES] = N_EDGES;
    }
}

__global__ __launch_bounds__(256) void place_kernel(const int* __restrict__ ei32) {
    const int stride = g_is64 ? 2 : 1;
    const long long dstbase = g_is64 ? (2LL * N_EDGES) : (long long)N_EDGES;
    int base = 4 * (blockIdx.x * blockDim.x + threadIdx.x);
    #pragma unroll
    for (int j = 0; j < 4; j++) {
        int e = base + j;
        if (e < N_EDGES) {
            int s = ei32[(long long)stride * e];
            int d = ei32[dstbase + (long long)stride * e];
            int slot = atomicAdd(&g_cur[d], 1);
            g_esrc[slot] = s;
        }
    }
}

// ---------------------------------------------------------------------------
// Gather: one block per dst node, thread = feature column. No atomics.
#define ETILE 128
__global__ __launch_bounds__(128) void gather_kernel(
    const float* __restrict__ b, float* __restrict__ out)
{
    __shared__ int   ss[ETILE];
    __shared__ float sv[ETILE];

    const int d = blockIdx.x;
    const int c = threadIdx.x;
    const int start = g_rowptr[d];
    const int end   = g_rowptr[d + 1];
    const float dinv_d = g_dinv[d];

    float acc = dinv_d * g_h[(size_t)d * NF + c];   // self loop

    for (int t = start; t < end; t += ETILE) {
        const int n = min(ETILE, end - t);
        if (c < n) {
            int s = g_esrc[t + c];
            ss[c] = s;
            sv[c] = g_dinv[s];
        }
        __syncthreads();
        for (int j = 0; j < n; j++) {
            acc = fmaf(g_h[(size_t)ss[j] * NF + c], sv[j], acc);
        }
        __syncthreads();
    }

    out[(size_t)d * NF + c] = b[c] + dinv_d * acc;
}

// ---------------------------------------------------------------------------
extern "C" void kernel_launch(void* const* d_in, const int* in_sizes, int n_in,
                              void* d_out, int out_size) {
    const float* x    = (const float*)d_in[0];
    const int*   ei32 = (const int*)d_in[1];
    const float* W    = (const float*)d_in[2];
    const float* b    = (const float*)d_in[3];
    float*       out  = (float*)d_out;

    detect_idx_kernel<<<1, 32>>>(ei32);                        // 1
    wfrag_kernel<<<32, 256>>>(W);                              // 2
    zero_cnt_kernel<<<(N_NODES + 255) / 256, 256>>>();         // 3
    // position 4: ncu capture slot -> profile the GEMM
    gemm_kernel<<<(N_NODES + GM - 1) / GM, 256>>>(x);          // 4
    count_deg_kernel<<<(N_EDGES / 4 + 255) / 256, 256>>>(ei32);
    scan_a_kernel<<<SCAN_NBLK, SCAN_B>>>();
    scan_b_kernel<<<1, 32>>>();
    scan_c_kernel<<<(N_NODES + 255) / 256, 256>>>();
    place_kernel<<<(N_EDGES / 4 + 255) / 256, 256>>>(ei32);
    gather_kernel<<<N_NODES, 128>>>(b, out);
}